// round 9
// baseline (speedup 1.0000x reference)
#include <cuda_runtime.h>
#include <mma.h>
#include <math.h>

using namespace nvcuda;

// ---------------------------------------------------------------------------
// RiemannianGNN, 2-layer Poincare GNN — split kernels, algebra-optimized.
//   gemm:  msg_raw = x @ W            (pure tf32 WMMA, no masks, no epilogue)
//   agg:   combined = sum_k (w*maskfac[adj]) * msg_raw[adj],  * mask[n]
//          out = relu(expmap(.)*mask)*mask   (+ fused logmap*mask for layer 0)
// Agg gather uses 4x LDG.32 per row (1 line each): L1 wavefronts stream at the
// 1.0 cyc cross-LDG rate instead of 2.07 cyc within-LDG replay rate.
// ---------------------------------------------------------------------------

#define NMAX 50000
#define DD 128
#define KK 32
#define LDSW 132        // padded W stride (floats)
#define TROWS 64        // rows per gemm tile

__device__ __align__(16) float g_msg[NMAX * DD];
__device__ __align__(16) float g_x[NMAX * DD];

// ---------------- persistent pure GEMM: out = x @ W ------------------------
__global__ __launch_bounds__(256) void gemm_kernel(
    const float* __restrict__ x, const float* __restrict__ W,
    float* __restrict__ out, int N)
{
    extern __shared__ float Ws[];   // 128 x LDSW
    const int tid = threadIdx.x;

    // stage W once (convert to tf32)
    for (int i = tid; i < DD * DD / 4; i += 256) {
        int r = i >> 5, c4 = i & 31;
        float4 v = ((const float4*)W)[r * 32 + c4];
        float* dst = Ws + r * LDSW + c4 * 4;
        dst[0] = wmma::__float_to_tf32(v.x);
        dst[1] = wmma::__float_to_tf32(v.y);
        dst[2] = wmma::__float_to_tf32(v.z);
        dst[3] = wmma::__float_to_tf32(v.w);
    }
    __syncthreads();   // the ONLY barrier in this kernel

    const int w  = tid >> 5;
    const int rw = w >> 1;       // row group: rows rw*16
    const int cw = w & 1;        // col group: cols cw*64

    const int nTiles = (N + TROWS - 1) / TROWS;

    for (int tile = blockIdx.x; tile < nTiles; tile += gridDim.x) {
        const int r0 = tile * TROWS + rw * 16;
        if (r0 + 16 > N) continue;          // N % 16 == 0: full groups only

        wmma::fragment<wmma::matrix_a, 16, 16, 8, wmma::precision::tf32, wmma::row_major> aF;
        wmma::fragment<wmma::matrix_b, 16, 16, 8, wmma::precision::tf32, wmma::row_major> bF[4];
        wmma::fragment<wmma::accumulator, 16, 16, 8, float> acc[4];
        #pragma unroll
        for (int j = 0; j < 4; j++) wmma::fill_fragment(acc[j], 0.0f);

        #pragma unroll
        for (int ks = 0; ks < DD / 8; ks++) {
            const int kOff = ks * 8;
            // A fragment straight from global (rows stream once; L2-backed)
            wmma::load_matrix_sync(aF, x + (size_t)r0 * DD + kOff, DD);
            #pragma unroll
            for (int j = 0; j < 4; j++)
                wmma::load_matrix_sync(bF[j], Ws + kOff * LDSW + cw * 64 + j * 16, LDSW);
            #pragma unroll
            for (int j = 0; j < 4; j++)
                wmma::mma_sync(acc[j], aF, bF[j], acc[j]);
        }

        #pragma unroll
        for (int j = 0; j < 4; j++)
            wmma::store_matrix_sync(out + (size_t)r0 * DD + cw * 64 + j * 16,
                                    acc[j], DD, wmma::mem_row_major);
    }
}

// ---------------- Aggregation + expmap + relu (+ fused logmap) -------------
// one warp per node; lane l holds cols {l, 32+l, 64+l, 96+l}.
// 4 independent LDG.32 per gathered row: each is one 128B line / 1 wavefront.
__global__ __launch_bounds__(256, 8) void agg_kernel(
    const float* __restrict__ msg, const int* __restrict__ adj,
    const float* __restrict__ wgt, const float* __restrict__ mask,
    float* __restrict__ out, int N, int layer0)
{
    const int warp = (blockIdx.x * blockDim.x + threadIdx.x) >> 5;
    const int lane = threadIdx.x & 31;
    if (warp >= N) return;

    const int   myIdx = adj[warp * KK + lane];
    const float ma    = mask[myIdx];
    // fold t-mask and msg-mask of the gathered rows into the weight
    const float myW   = wgt[warp * KK + lane] * (layer0 ? ma * ma : ma);

    float a0 = 0.f, a1 = 0.f, a2 = 0.f, a3 = 0.f;
    #pragma unroll
    for (int j = 0; j < KK; j++) {
        int   nb = __shfl_sync(0xffffffffu, myIdx, j);
        float wj = __shfl_sync(0xffffffffu, myW,   j);
        const float* row = msg + (size_t)nb * DD + lane;
        float v0 = __ldg(row);
        float v1 = __ldg(row + 32);
        float v2 = __ldg(row + 64);
        float v3 = __ldg(row + 96);
        a0 = fmaf(wj, v0, a0);
        a1 = fmaf(wj, v1, a1);
        a2 = fmaf(wj, v2, a2);
        a3 = fmaf(wj, v3, a3);
    }

    const float m = mask[warp];
    a0 *= m; a1 *= m; a2 *= m; a3 *= m;      // combined = (...)*mask

    // expmap_zero: tanh(clip(||v||,eps,15)) * v / max(||v||,eps), then *mask
    float ss = a0 * a0 + a1 * a1 + a2 * a2 + a3 * a3;
    #pragma unroll
    for (int o = 16; o > 0; o >>= 1) ss += __shfl_xor_sync(0xffffffffu, ss, o);
    float n1  = sqrtf(ss);
    float nc1 = fminf(fmaxf(n1, 1e-5f), 15.0f);
    float s1  = tanhf(nc1) / fmaxf(n1, 1e-5f) * m;

    float e0 = fmaxf(a0 * s1, 0.f) * m;      // relu(...)*mask
    float e1 = fmaxf(a1 * s1, 0.f) * m;
    float e2 = fmaxf(a2 * s1, 0.f) * m;
    float e3 = fmaxf(a3 * s1, 0.f) * m;

    if (layer0) {
        // next layer's logmap: atanh(clip(||y||,eps,1-1e-5))*y/max(||y||,eps) * mask
        float ss2 = e0 * e0 + e1 * e1 + e2 * e2 + e3 * e3;
        #pragma unroll
        for (int o = 16; o > 0; o >>= 1) ss2 += __shfl_xor_sync(0xffffffffu, ss2, o);
        float n2  = sqrtf(ss2);
        float nc2 = fminf(fmaxf(n2, 1e-5f), 1.0f - 1e-5f);
        float s2  = atanhf(nc2) / fmaxf(n2, 1e-5f) * m;
        e0 *= s2; e1 *= s2; e2 *= s2; e3 *= s2;
    }

    float* orow = out + (size_t)warp * DD + lane;
    orow[0]  = e0;
    orow[32] = e1;
    orow[64] = e2;
    orow[96] = e3;
}

// ---------------------------------------------------------------------------

extern "C" void kernel_launch(void* const* d_in, const int* in_sizes, int n_in,
                              void* d_out, int out_size)
{
    const float* node_repr = (const float*)d_in[0];   // [N,128]
    const int*   adj_mat   = (const int*)  d_in[1];   // [N,32]
    const float* weight    = (const float*)d_in[2];   // [N,32]
    const float* mask      = (const float*)d_in[3];   // [N,1]
    const float* msg_w     = (const float*)d_in[4];   // [2,128,128]
    float*       out       = (float*)d_out;

    const int N = in_sizes[0] / DD;

    float* msg; float* xbuf;
    cudaGetSymbolAddress((void**)&msg,  g_msg);
    cudaGetSymbolAddress((void**)&xbuf, g_x);

    const int smemBytes = DD * LDSW * sizeof(float);   // 67.6 KB -> 2 CTA/SM
    static int attrSet = 0;
    if (!attrSet) {
        cudaFuncSetAttribute(gemm_kernel,
                             cudaFuncAttributeMaxDynamicSharedMemorySize, smemBytes);
        attrSet = 1;
    }

    const int nTiles = (N + TROWS - 1) / TROWS;
    int gemmBlocks = 296;                // persistent, 2 CTA/SM
    if (gemmBlocks > nTiles) gemmBlocks = nTiles;
    const int aggBlocks = (N * 32 + 255) / 256;

    const float* W0 = msg_w;
    const float* W1 = msg_w + DD * DD;

    // layer 0: msg = node_repr @ W0 (pure); agg folds masks, fuses logmap
    gemm_kernel<<<gemmBlocks, 256, smemBytes>>>(node_repr, W0, msg, N);
    agg_kernel <<<aggBlocks, 256>>>(msg, adj_mat, weight, mask, xbuf, N, 1);
    // layer 1
    gemm_kernel<<<gemmBlocks, 256, smemBytes>>>(xbuf, W1, msg, N);
    agg_kernel <<<aggBlocks, 256>>>(msg, adj_mat, weight, mask, out, N, 0);
}

// round 10
// speedup vs baseline: 1.1829x; 1.1829x over previous
#include <cuda_runtime.h>
#include <mma.h>
#include <math.h>

using namespace nvcuda;

// ---------------------------------------------------------------------------
// RiemannianGNN, 2-layer Poincare GNN — split kernels.
//   gemm:  msg = x @ W          (tf32 WMMA, W resident, cp.async-pipelined A)
//   agg:   combined = sum_k (w*maskfac[adj]) * msg[adj],  * mask[n]
//          out = relu(expmap(.)*mask)*mask  (+ fused logmap*mask for layer 0)
// ---------------------------------------------------------------------------

#define NMAX 50000
#define DD 128
#define KK 32
#define LDSW 132        // padded W stride (floats); 528B = 33*16B (wmma-legal)
#define LDSA 132        // padded A stride
#define ATILE 32        // rows per pipelined A tile

__device__ __align__(16) float g_msg[NMAX * DD];
__device__ __align__(16) float g_x[NMAX * DD];

__device__ __forceinline__ void cp_async16(float* smem_dst, const float* gsrc) {
    unsigned s = (unsigned)__cvta_generic_to_shared(smem_dst);
    asm volatile("cp.async.cg.shared.global [%0], [%1], 16;" :: "r"(s), "l"(gsrc));
}
__device__ __forceinline__ void cp_commit() {
    asm volatile("cp.async.commit_group;");
}
__device__ __forceinline__ void cp_wait1() {
    asm volatile("cp.async.wait_group 1;");
}

// ---------------- persistent pipelined GEMM: out = x @ W -------------------
// 8 warps: rw = w>>2 (rows rw*16), cw = w&3 (cols cw*32)
__global__ __launch_bounds__(256) void gemm_kernel(
    const float* __restrict__ x, const float* __restrict__ W,
    float* __restrict__ out, int N)
{
    extern __shared__ float sm[];
    float* Ws = sm;                          // 128 x LDSW
    float* A0 = sm + DD * LDSW;              // ATILE x LDSA
    float* A1 = A0 + ATILE * LDSA;           // ATILE x LDSA

    const int tid = threadIdx.x;

    // stage W once (convert to tf32)
    for (int i = tid; i < DD * DD / 4; i += 256) {
        int r = i >> 5, c4 = i & 31;
        float4 v = ((const float4*)W)[r * 32 + c4];
        float* dst = Ws + r * LDSW + c4 * 4;
        dst[0] = wmma::__float_to_tf32(v.x);
        dst[1] = wmma::__float_to_tf32(v.y);
        dst[2] = wmma::__float_to_tf32(v.z);
        dst[3] = wmma::__float_to_tf32(v.w);
    }

    const int w  = tid >> 5;
    const int rw = w >> 2;       // 0..1 : rows rw*16
    const int cw = w & 3;        // 0..3 : cols cw*32

    const int nTiles = (N + ATILE - 1) / ATILE;

    // per-thread slice of the A-tile copy: 4 float4 (32 rows * 32 f4 / 256 thr)
    auto loadA = [&](int t0, float* buf) {
        #pragma unroll
        for (int i = 0; i < 4; i++) {
            int idx = tid + i * 256;
            int r = idx >> 5, c4 = idx & 31;
            int n = t0 + r;
            float* dst = buf + r * LDSA + c4 * 4;
            if (n < N) {
                cp_async16(dst, x + (size_t)n * DD + c4 * 4);
            } else {
                dst[0] = 0.f; dst[1] = 0.f; dst[2] = 0.f; dst[3] = 0.f;
            }
        }
    };

    // prologue: prefetch first tile
    int tile = blockIdx.x;
    if (tile < nTiles) loadA(tile * ATILE, A0);
    cp_commit();
    __syncthreads();     // W ready + first tile committed by all

    int p = 0;
    for (; tile < nTiles; tile += gridDim.x) {
        const int nt = tile + gridDim.x;
        if (nt < nTiles) loadA(nt * ATILE, p ? A0 : A1);
        cp_commit();                 // (possibly empty) group
        cp_wait1();                  // current tile's group complete
        __syncthreads();

        const float* Ab = p ? A1 : A0;
        const int t0 = tile * ATILE;

        wmma::fragment<wmma::matrix_a, 16, 16, 8, wmma::precision::tf32, wmma::row_major> aF;
        wmma::fragment<wmma::matrix_b, 16, 16, 8, wmma::precision::tf32, wmma::row_major> bF[2];
        wmma::fragment<wmma::accumulator, 16, 16, 8, float> acc[2];
        #pragma unroll
        for (int j = 0; j < 2; j++) wmma::fill_fragment(acc[j], 0.0f);

        #pragma unroll
        for (int ks = 0; ks < DD / 8; ks++) {
            const int kOff = ks * 8;
            wmma::load_matrix_sync(aF, Ab + (rw * 16) * LDSA + kOff, LDSA);
            #pragma unroll
            for (int j = 0; j < 2; j++)
                wmma::load_matrix_sync(bF[j], Ws + kOff * LDSW + cw * 32 + j * 16, LDSW);
            #pragma unroll
            for (int j = 0; j < 2; j++)
                wmma::mma_sync(acc[j], aF, bF[j], acc[j]);
        }

        const int r0 = t0 + rw * 16;
        if (r0 + 16 <= N) {          // N%16==0: row-group fully valid or fully out
            #pragma unroll
            for (int j = 0; j < 2; j++)
                wmma::store_matrix_sync(out + (size_t)r0 * DD + cw * 32 + j * 16,
                                        acc[j], DD, wmma::mem_row_major);
        }
        __syncthreads();             // all reads of Ab done before it's refilled
        p ^= 1;
    }
}

// ---------------- Aggregation + expmap + relu (+ fused logmap) -------------
// one warp per node; lane l holds cols 4l..4l+3 (LDG.128 per gathered row)
__global__ __launch_bounds__(256, 8) void agg_kernel(
    const float* __restrict__ msg, const int* __restrict__ adj,
    const float* __restrict__ wgt, const float* __restrict__ mask,
    float* __restrict__ out, int N, int layer0)
{
    const int warp = (blockIdx.x * blockDim.x + threadIdx.x) >> 5;
    const int lane = threadIdx.x & 31;
    if (warp >= N) return;

    const int   myIdx = adj[warp * KK + lane];
    const float ma    = mask[myIdx];
    // fold t-mask and msg-mask of the gathered rows into the weight
    const float myW   = wgt[warp * KK + lane] * (layer0 ? ma * ma : ma);

    float4 acc = make_float4(0.f, 0.f, 0.f, 0.f);
    #pragma unroll
    for (int j = 0; j < KK; j++) {
        int   nb = __shfl_sync(0xffffffffu, myIdx, j);
        float wj = __shfl_sync(0xffffffffu, myW,   j);
        float4 v = __ldg(((const float4*)(msg + (size_t)nb * DD)) + lane);
        acc.x = fmaf(wj, v.x, acc.x);
        acc.y = fmaf(wj, v.y, acc.y);
        acc.z = fmaf(wj, v.z, acc.z);
        acc.w = fmaf(wj, v.w, acc.w);
    }

    const float m = mask[warp];
    acc.x *= m; acc.y *= m; acc.z *= m; acc.w *= m;   // combined = (...)*mask

    // expmap_zero: tanh(clip(||v||,eps,15)) * v / max(||v||,eps), then *mask
    float ss = acc.x * acc.x + acc.y * acc.y + acc.z * acc.z + acc.w * acc.w;
    #pragma unroll
    for (int o = 16; o > 0; o >>= 1) ss += __shfl_xor_sync(0xffffffffu, ss, o);
    float n1  = sqrtf(ss);
    float nc1 = fminf(fmaxf(n1, 1e-5f), 15.0f);
    float s1  = tanhf(nc1) / fmaxf(n1, 1e-5f) * m;

    float4 e;
    e.x = fmaxf(acc.x * s1, 0.f) * m;
    e.y = fmaxf(acc.y * s1, 0.f) * m;
    e.z = fmaxf(acc.z * s1, 0.f) * m;
    e.w = fmaxf(acc.w * s1, 0.f) * m;

    if (layer0) {
        // next layer's logmap: atanh(clip(||y||,eps,1-1e-5))*y/max(||y||,eps)*mask
        float ss2 = e.x * e.x + e.y * e.y + e.z * e.z + e.w * e.w;
        #pragma unroll
        for (int o = 16; o > 0; o >>= 1) ss2 += __shfl_xor_sync(0xffffffffu, ss2, o);
        float n2  = sqrtf(ss2);
        float nc2 = fminf(fmaxf(n2, 1e-5f), 1.0f - 1e-5f);
        float s2  = atanhf(nc2) / fmaxf(n2, 1e-5f) * m;
        e.x *= s2; e.y *= s2; e.z *= s2; e.w *= s2;
    }

    ((float4*)out)[warp * 32 + lane] = e;
}

// ---------------------------------------------------------------------------

extern "C" void kernel_launch(void* const* d_in, const int* in_sizes, int n_in,
                              void* d_out, int out_size)
{
    const float* node_repr = (const float*)d_in[0];   // [N,128]
    const int*   adj_mat   = (const int*)  d_in[1];   // [N,32]
    const float* weight    = (const float*)d_in[2];   // [N,32]
    const float* mask      = (const float*)d_in[3];   // [N,1]
    const float* msg_w     = (const float*)d_in[4];   // [2,128,128]
    float*       out       = (float*)d_out;

    const int N = in_sizes[0] / DD;

    float* msg; float* xbuf;
    cudaGetSymbolAddress((void**)&msg,  g_msg);
    cudaGetSymbolAddress((void**)&xbuf, g_x);

    const int smemBytes = (DD * LDSW + 2 * ATILE * LDSA) * sizeof(float); // ~101.4 KB
    static int attrSet = 0;
    if (!attrSet) {
        cudaFuncSetAttribute(gemm_kernel,
                             cudaFuncAttributeMaxDynamicSharedMemorySize, smemBytes);
        // agg uses no smem: maximize L1 to raise gather hit rate
        cudaFuncSetAttribute(agg_kernel,
                             cudaFuncAttributePreferredSharedMemoryCarveout, 0);
        attrSet = 1;
    }

    const int nTiles = (N + ATILE - 1) / ATILE;
    int gemmBlocks = 296;                // persistent, 2 CTA/SM
    if (gemmBlocks > nTiles) gemmBlocks = nTiles;
    const int aggBlocks = (N * 32 + 255) / 256;

    const float* W0 = msg_w;
    const float* W1 = msg_w + DD * DD;

    gemm_kernel<<<gemmBlocks, 256, smemBytes>>>(node_repr, W0, msg, N);
    agg_kernel <<<aggBlocks, 256>>>(msg, adj_mat, weight, mask, xbuf, N, 1);
    gemm_kernel<<<gemmBlocks, 256, smemBytes>>>(xbuf, W1, msg, N);
    agg_kernel <<<aggBlocks, 256>>>(msg, adj_mat, weight, mask, out, N, 0);
}